// round 3
// baseline (speedup 1.0000x reference)
#include <cuda_runtime.h>
#include <math.h>

// ---------------------------------------------------------------------------
// MySelfAttention_V2: B=4, N=4096, D=768 single-head attention, fp32.
//   qkv = x @ w_qkv + b_qkv            [16384 x 2304]
//   S   = softmax(Q K^T / sqrt(D))     per batch [4096 x 4096]
//   ctx = S @ V                        [16384 x 768]
//   out = ctx @ w_out + b_out          [16384 x 768]
// All dims divide the 128x128x16 GEMM tile exactly -> no bounds checks.
// ---------------------------------------------------------------------------

#define B_   4
#define N_   4096
#define D_   768
#define QKVC 2304                      // 3*D
#define SCALE_F 0.03608439182435161f   // 1/sqrt(768)

// Scratch (static device globals: allocation-guard-safe)
__device__ float g_qkv[(size_t)B_ * N_ * QKVC];   // 151 MB
__device__ float g_s  [(size_t)B_ * N_ * N_];     // 268 MB
__device__ float g_ctx[(size_t)B_ * N_ * D_];     //  48 MB

// ---------------------------------------------------------------------------
// SGEMM: C[m,n] = alpha * sum_k A[m,k]*B(k,n) (+ bias[n])
//   TRANSB=false : B row-major [K x Ncols], B(k,n) = Bm[k*ldb + n]
//   TRANSB=true  : B row-major [Ncols x K], B(k,n) = Bm[n*ldb + k]
// Tiles: BM=BN=128, BK=16, 256 threads, 8x8 accum/thread,
// register-double-buffered global->smem pipeline.
// ---------------------------------------------------------------------------
template <bool TRANSB, bool HAS_BIAS>
__global__ __launch_bounds__(256, 2)
void sgemm_kernel(const float* __restrict__ A, const float* __restrict__ Bm,
                  const float* __restrict__ bias, float* __restrict__ C,
                  int K, int lda, int ldb, int ldc,
                  long long sA, long long sB, long long sC, float alpha)
{
    __shared__ float As[16][128];
    __shared__ float Bs[16][128];

    A  += (long long)blockIdx.z * sA;
    Bm += (long long)blockIdx.z * sB;
    C  += (long long)blockIdx.z * sC;

    const int m0  = blockIdx.y * 128;
    const int n0  = blockIdx.x * 128;
    const int tid = threadIdx.x;
    const int tx  = tid & 15;          // 0..15 -> column group
    const int ty  = tid >> 4;          // 0..15 -> row group

    // ---- global-load index precompute ----
    // A (and B when TRANSB): two float4 per thread, rows r and r+64
    const int arow = tid >> 2;          // 0..63
    const int ac4  = (tid & 3) << 2;    // 0,4,8,12
    // B when !TRANSB: [16 x 128] tile, two float4 per thread
    const int bkk  = tid >> 5;          // 0..7
    const int bn4  = (tid & 31) << 2;   // 0..124

    float acc[8][8];
#pragma unroll
    for (int i = 0; i < 8; i++)
#pragma unroll
        for (int j = 0; j < 8; j++) acc[i][j] = 0.0f;

    float4 pa0, pa1, pb0, pb1;

#define LOAD_TILE_REGS(k0)                                                          \
    do {                                                                            \
        pa0 = *(const float4*)(A + (long long)(m0 + arow)      * lda + (k0) + ac4); \
        pa1 = *(const float4*)(A + (long long)(m0 + arow + 64) * lda + (k0) + ac4); \
        if (TRANSB) {                                                               \
            pb0 = *(const float4*)(Bm + (long long)(n0 + arow)      * ldb + (k0) + ac4); \
            pb1 = *(const float4*)(Bm + (long long)(n0 + arow + 64) * ldb + (k0) + ac4); \
        } else {                                                                    \
            pb0 = *(const float4*)(Bm + (long long)((k0) + bkk)     * ldb + n0 + bn4);   \
            pb1 = *(const float4*)(Bm + (long long)((k0) + bkk + 8) * ldb + n0 + bn4);   \
        }                                                                           \
    } while (0)

#define STORE_TILE_SMEM()                                                           \
    do {                                                                            \
        As[ac4 + 0][arow] = pa0.x; As[ac4 + 1][arow] = pa0.y;                       \
        As[ac4 + 2][arow] = pa0.z; As[ac4 + 3][arow] = pa0.w;                       \
        As[ac4 + 0][arow + 64] = pa1.x; As[ac4 + 1][arow + 64] = pa1.y;             \
        As[ac4 + 2][arow + 64] = pa1.z; As[ac4 + 3][arow + 64] = pa1.w;             \
        if (TRANSB) {                                                               \
            Bs[ac4 + 0][arow] = pb0.x; Bs[ac4 + 1][arow] = pb0.y;                   \
            Bs[ac4 + 2][arow] = pb0.z; Bs[ac4 + 3][arow] = pb0.w;                   \
            Bs[ac4 + 0][arow + 64] = pb1.x; Bs[ac4 + 1][arow + 64] = pb1.y;         \
            Bs[ac4 + 2][arow + 64] = pb1.z; Bs[ac4 + 3][arow + 64] = pb1.w;         \
        } else {                                                                    \
            *(float4*)&Bs[bkk][bn4]     = pb0;                                      \
            *(float4*)&Bs[bkk + 8][bn4] = pb1;                                      \
        }                                                                           \
    } while (0)

    // prologue: tile 0 -> smem
    LOAD_TILE_REGS(0);
    STORE_TILE_SMEM();
    __syncthreads();

    for (int k0 = 0; k0 < K; k0 += 16) {
        const bool has_next = (k0 + 16) < K;
        if (has_next) LOAD_TILE_REGS(k0 + 16);

#pragma unroll
        for (int kk = 0; kk < 16; kk++) {
            const float4 a0 = *(const float4*)&As[kk][ty * 4];
            const float4 a1 = *(const float4*)&As[kk][ty * 4 + 64];
            const float4 b0 = *(const float4*)&Bs[kk][tx * 4];
            const float4 b1 = *(const float4*)&Bs[kk][tx * 4 + 64];
            const float ar[8] = {a0.x, a0.y, a0.z, a0.w, a1.x, a1.y, a1.z, a1.w};
            const float br[8] = {b0.x, b0.y, b0.z, b0.w, b1.x, b1.y, b1.z, b1.w};
#pragma unroll
            for (int i = 0; i < 8; i++)
#pragma unroll
                for (int j = 0; j < 8; j++)
                    acc[i][j] = fmaf(ar[i], br[j], acc[i][j]);
        }

        if (has_next) {
            __syncthreads();
            STORE_TILE_SMEM();
            __syncthreads();
        }
    }

    // ---- epilogue ----
    float bj[8];
    if (HAS_BIAS) {
#pragma unroll
        for (int j = 0; j < 4; j++) {
            bj[j]     = bias[n0 + tx * 4 + j];
            bj[4 + j] = bias[n0 + tx * 4 + 64 + j];
        }
    } else {
#pragma unroll
        for (int j = 0; j < 8; j++) bj[j] = 0.0f;
    }

#pragma unroll
    for (int i = 0; i < 8; i++) {
        const int row = m0 + ((i < 4) ? (ty * 4 + i) : (ty * 4 + 60 + i));
        float4 o0, o1;
        o0.x = fmaf(alpha, acc[i][0], bj[0]);
        o0.y = fmaf(alpha, acc[i][1], bj[1]);
        o0.z = fmaf(alpha, acc[i][2], bj[2]);
        o0.w = fmaf(alpha, acc[i][3], bj[3]);
        o1.x = fmaf(alpha, acc[i][4], bj[4]);
        o1.y = fmaf(alpha, acc[i][5], bj[5]);
        o1.z = fmaf(alpha, acc[i][6], bj[6]);
        o1.w = fmaf(alpha, acc[i][7], bj[7]);
        *(float4*)(C + (long long)row * ldc + n0 + tx * 4)      = o0;
        *(float4*)(C + (long long)row * ldc + n0 + tx * 4 + 64) = o1;
    }
#undef LOAD_TILE_REGS
#undef STORE_TILE_SMEM
}

// ---------------------------------------------------------------------------
// Row softmax over S: one block per row of 4096 floats. 256 thr x 16 elems.
// ---------------------------------------------------------------------------
__global__ __launch_bounds__(256)
void softmax_kernel(float* __restrict__ S)
{
    float* p = S + (size_t)blockIdx.x * N_;
    const int tid = threadIdx.x;
    const int w = tid >> 5, l = tid & 31;

    float4 v[4];
#pragma unroll
    for (int i = 0; i < 4; i++)
        v[i] = *(const float4*)(p + (size_t)(tid + i * 256) * 4);

    float m = v[0].x;
#pragma unroll
    for (int i = 0; i < 4; i++) {
        m = fmaxf(m, v[i].x); m = fmaxf(m, v[i].y);
        m = fmaxf(m, v[i].z); m = fmaxf(m, v[i].w);
    }
#pragma unroll
    for (int o = 16; o > 0; o >>= 1)
        m = fmaxf(m, __shfl_xor_sync(0xffffffffu, m, o));

    __shared__ float red[8];
    if (l == 0) red[w] = m;
    __syncthreads();
    float bm = red[0];
#pragma unroll
    for (int i = 1; i < 8; i++) bm = fmaxf(bm, red[i]);
    __syncthreads();

    float s = 0.0f;
#pragma unroll
    for (int i = 0; i < 4; i++) {
        v[i].x = expf(v[i].x - bm); s += v[i].x;
        v[i].y = expf(v[i].y - bm); s += v[i].y;
        v[i].z = expf(v[i].z - bm); s += v[i].z;
        v[i].w = expf(v[i].w - bm); s += v[i].w;
    }
#pragma unroll
    for (int o = 16; o > 0; o >>= 1)
        s += __shfl_xor_sync(0xffffffffu, s, o);
    if (l == 0) red[w] = s;
    __syncthreads();
    float tot = red[0];
#pragma unroll
    for (int i = 1; i < 8; i++) tot += red[i];
    const float inv = 1.0f / tot;

#pragma unroll
    for (int i = 0; i < 4; i++) {
        v[i].x *= inv; v[i].y *= inv; v[i].z *= inv; v[i].w *= inv;
        *(float4*)(p + (size_t)(tid + i * 256) * 4) = v[i];
    }
}

// ---------------------------------------------------------------------------
extern "C" void kernel_launch(void* const* d_in, const int* in_sizes, int n_in,
                              void* d_out, int out_size)
{
    const float* x     = (const float*)d_in[0];
    const float* w_qkv = (const float*)d_in[1];
    const float* b_qkv = (const float*)d_in[2];
    const float* w_out = (const float*)d_in[3];
    const float* b_out = (const float*)d_in[4];
    float* out = (float*)d_out;

    float *qkv, *S, *ctx;
    cudaGetSymbolAddress((void**)&qkv, g_qkv);
    cudaGetSymbolAddress((void**)&S,   g_s);
    cudaGetSymbolAddress((void**)&ctx, g_ctx);

    const dim3 blk(256);

    // 1) qkv = x @ w_qkv + b_qkv        [16384 x 2304]
    sgemm_kernel<false, true><<<dim3(QKVC / 128, (B_ * N_) / 128, 1), blk>>>(
        x, w_qkv, b_qkv, qkv, D_, D_, QKVC, QKVC, 0, 0, 0, 1.0f);

    // 2) S = scale * Q @ K^T            per batch [4096 x 4096]
    sgemm_kernel<true, false><<<dim3(N_ / 128, N_ / 128, B_), blk>>>(
        qkv, qkv + D_, nullptr, S, D_, QKVC, QKVC, N_,
        (long long)N_ * QKVC, (long long)N_ * QKVC, (long long)N_ * N_, SCALE_F);

    // 3) row softmax over S
    softmax_kernel<<<B_ * N_, blk>>>(S);

    // 4) ctx = S @ V                    per batch [4096 x 768]
    sgemm_kernel<false, false><<<dim3(D_ / 128, N_ / 128, B_), blk>>>(
        S, qkv + 2 * D_, nullptr, ctx, N_, N_, QKVC, D_,
        (long long)N_ * N_, (long long)N_ * QKVC, (long long)N_ * D_, 1.0f);

    // 5) out = ctx @ w_out + b_out      [16384 x 768]
    sgemm_kernel<false, true><<<dim3(D_ / 128, (B_ * N_) / 128, 1), blk>>>(
        ctx, w_out, b_out, out, D_, D_, D_, D_, 0, 0, 0, 1.0f);
}

// round 5
// speedup vs baseline: 2.3412x; 2.3412x over previous
#include <cuda_runtime.h>
#include <cuda_bf16.h>
#include <stdint.h>
#include <math.h>

// ---------------------------------------------------------------------------
// MySelfAttention_V2 (B=4, N=4096, D=768) — mma.sync bf16 hi/lo split (3-pass)
//   qkv = x @ w_qkv + b_qkv ; S = softmax(QK^T/sqrt(D)) ; ctx = S@V ;
//   out = ctx @ w_out + b_out
// GEMM: C = alpha * A*B^T (+bias), A,B as bf16 (hi,lo) pairs, fp32 accum:
//   A*B ≈ Ah*Bh + Ah*Bl + Al*Bh     (dropped term ~2^-18 rel)
// ---------------------------------------------------------------------------

#define B_   4
#define N_   4096
#define D_   768
#define QKVC 2304
#define SCALE_F 0.03608439182435161f

typedef __nv_bfloat16 bf16;

// ---------------- scratch (static device globals: allocation-guard-safe) ----
__device__ float g_qkv [(size_t)B_ * N_ * QKVC];
__device__ float g_s   [(size_t)B_ * N_ * N_];
__device__ float g_ctx [(size_t)B_ * N_ * D_];
__device__ bf16  g_xh  [(size_t)B_ * N_ * D_],   g_xl  [(size_t)B_ * N_ * D_];
__device__ bf16  g_qh  [(size_t)B_ * N_ * QKVC], g_ql  [(size_t)B_ * N_ * QKVC];
__device__ bf16  g_sh  [(size_t)B_ * N_ * N_],   g_sl  [(size_t)B_ * N_ * N_];
__device__ bf16  g_vth [(size_t)B_ * D_ * N_],   g_vtl [(size_t)B_ * D_ * N_];
__device__ bf16  g_ch  [(size_t)B_ * N_ * D_],   g_cl  [(size_t)B_ * N_ * D_];
__device__ bf16  g_wqh [(size_t)QKVC * D_],      g_wql [(size_t)QKVC * D_];
__device__ bf16  g_woh [(size_t)D_ * D_],        g_wol [(size_t)D_ * D_];

// ---------------- PTX helpers ----------------------------------------------
static __device__ __forceinline__ uint32_t smem_u32(const void* p) {
    uint32_t a;
    asm("{ .reg .u64 t; cvta.to.shared.u64 t, %1; cvt.u32.u64 %0, t; }"
        : "=r"(a) : "l"(p));
    return a;
}
static __device__ __forceinline__ void cp_async16(uint32_t saddr, const void* g) {
    asm volatile("cp.async.cg.shared.global [%0], [%1], 16;"
                 :: "r"(saddr), "l"(g) : "memory");
}
static __device__ __forceinline__ void cp_commit() {
    asm volatile("cp.async.commit_group;" ::: "memory");
}
template <int N>
static __device__ __forceinline__ void cp_wait() {
    asm volatile("cp.async.wait_group %0;" :: "n"(N) : "memory");
}
static __device__ __forceinline__ void ldsm_x4(uint32_t* r, uint32_t addr) {
    asm volatile("ldmatrix.sync.aligned.m8n8.x4.shared.b16 {%0,%1,%2,%3}, [%4];"
                 : "=r"(r[0]), "=r"(r[1]), "=r"(r[2]), "=r"(r[3]) : "r"(addr));
}
static __device__ __forceinline__ void mma16816(float* c, const uint32_t* a,
                                                const uint32_t* b) {
    asm volatile(
        "mma.sync.aligned.m16n8k16.row.col.f32.bf16.bf16.f32 "
        "{%0,%1,%2,%3}, {%4,%5,%6,%7}, {%8,%9}, {%0,%1,%2,%3};"
        : "+f"(c[0]), "+f"(c[1]), "+f"(c[2]), "+f"(c[3])
        : "r"(a[0]), "r"(a[1]), "r"(a[2]), "r"(a[3]), "r"(b[0]), "r"(b[1]));
}
// hi/lo split of an fp32 into two bf16
static __device__ __forceinline__ void split1(float v, bf16& h, bf16& l) {
    h = __float2bfloat16_rn(v);
    l = __float2bfloat16_rn(v - __bfloat162float(h));
}
static __device__ __forceinline__ uint32_t pack2(bf16 a, bf16 b) {
    return (uint32_t)__bfloat16_as_ushort(a) |
           ((uint32_t)__bfloat16_as_ushort(b) << 16);
}

// ---------------------------------------------------------------------------
// GEMM: C[m,n] = alpha * sum_k A[m,k]*B[n,k]  (+bias[n])
// A,B bf16 hi/lo K-major. Tile 128x128, BK=32, 256 threads, 2-stage cp.async.
// Smem rows padded to 40 bf16 (80B) -> conflict-free ldmatrix.
// ---------------------------------------------------------------------------
#define RS 80                         // smem row stride bytes
#define TILE_B (128 * RS)             // 10240 B per matrix buffer
#define STAGE_B (4 * TILE_B)          // Ah,Al,Bh,Bl per stage
static const int SMEM_DYN = 2 * STAGE_B;   // 81920

template <bool HAS_BIAS>
__global__ __launch_bounds__(256)
void mma_gemm(const bf16* __restrict__ Ah, const bf16* __restrict__ Al,
              const bf16* __restrict__ Bh, const bf16* __restrict__ Bl,
              const float* __restrict__ bias, float* __restrict__ C,
              int K, int lda, int ldb, int ldc,
              long long sA, long long sB, long long sC, float alpha)
{
    extern __shared__ char smem[];
    const uint32_t sb = smem_u32(smem);

    Ah += blockIdx.z * sA;  Al += blockIdx.z * sA;
    Bh += blockIdx.z * sB;  Bl += blockIdx.z * sB;
    C  += blockIdx.z * sC;
    const int m0 = blockIdx.y * 128, n0 = blockIdx.x * 128;
    const int tid  = threadIdx.x;
    const int wid  = tid >> 5, lane = tid & 31;
    const int wm   = wid >> 2, wn = wid & 3;   // 2 x 4 warps

    // cp.async lane mapping: 2 chunks of 16B per matrix per thread
    const int cr0 = tid >> 2,        cc0 = (tid & 3);        // row 0..63,  chunk 0..3
    const int cr1 = 64 + (tid >> 2), cc1 = (tid & 3);        // row 64..127

#define LOAD_STAGE(st, k0)                                                     \
    do {                                                                       \
        const uint32_t s0 = sb + (st) * STAGE_B;                               \
        const long long kof = (k0);                                            \
        cp_async16(s0 + 0*TILE_B + cr0*RS + cc0*16, Ah + (long long)(m0+cr0)*lda + kof + cc0*8); \
        cp_async16(s0 + 0*TILE_B + cr1*RS + cc1*16, Ah + (long long)(m0+cr1)*lda + kof + cc1*8); \
        cp_async16(s0 + 1*TILE_B + cr0*RS + cc0*16, Al + (long long)(m0+cr0)*lda + kof + cc0*8); \
        cp_async16(s0 + 1*TILE_B + cr1*RS + cc1*16, Al + (long long)(m0+cr1)*lda + kof + cc1*8); \
        cp_async16(s0 + 2*TILE_B + cr0*RS + cc0*16, Bh + (long long)(n0+cr0)*ldb + kof + cc0*8); \
        cp_async16(s0 + 2*TILE_B + cr1*RS + cc1*16, Bh + (long long)(n0+cr1)*ldb + kof + cc1*8); \
        cp_async16(s0 + 3*TILE_B + cr0*RS + cc0*16, Bl + (long long)(n0+cr0)*ldb + kof + cc0*8); \
        cp_async16(s0 + 3*TILE_B + cr1*RS + cc1*16, Bl + (long long)(n0+cr1)*ldb + kof + cc1*8); \
    } while (0)

    // ldmatrix lane-relative offsets
    const uint32_t a_l = (uint32_t)((lane & 15) * RS + (lane >> 4) * 16);
    const uint32_t b_l = (uint32_t)((((lane & 7) + ((lane >> 4) << 3)) * RS) +
                                    (((lane >> 3) & 1) * 16));

    float acc[4][4][4];
#pragma unroll
    for (int mt = 0; mt < 4; mt++)
#pragma unroll
        for (int nt = 0; nt < 4; nt++)
#pragma unroll
            for (int r = 0; r < 4; r++) acc[mt][nt][r] = 0.0f;

    const int nch = K / 32;
    LOAD_STAGE(0, 0);
    cp_commit();

    for (int ch = 0; ch < nch; ch++) {
        const int st = ch & 1;
        if (ch + 1 < nch) { LOAD_STAGE(st ^ 1, (long long)(ch + 1) * 32); cp_commit(); cp_wait<1>(); }
        else              { cp_wait<0>(); }
        __syncthreads();

        const uint32_t base = sb + st * STAGE_B;
#pragma unroll
        for (int kk = 0; kk < 2; kk++) {
            const uint32_t ko = (uint32_t)(kk * 32);   // 16 bf16 = 32B
            uint32_t af[2][4][4];                      // [hl][mt][reg]
            uint32_t bfr[2][2][4];                     // [hl][pair][reg]
#pragma unroll
            for (int mt = 0; mt < 4; mt++) {
                const uint32_t ro = (uint32_t)((wm * 64 + mt * 16) * RS) + ko + a_l;
                ldsm_x4(af[0][mt], base + 0 * TILE_B + ro);
                ldsm_x4(af[1][mt], base + 1 * TILE_B + ro);
            }
#pragma unroll
            for (int p = 0; p < 2; p++) {
                const uint32_t ro = (uint32_t)((wn * 32 + p * 16) * RS) + ko + b_l;
                ldsm_x4(bfr[0][p], base + 2 * TILE_B + ro);
                ldsm_x4(bfr[1][p], base + 3 * TILE_B + ro);
            }
            // 3 passes: (Ah,Bh), (Ah,Bl), (Al,Bh)
#pragma unroll
            for (int ps = 0; ps < 3; ps++) {
                const int ah = (ps == 2), bh = (ps == 1);
#pragma unroll
                for (int mt = 0; mt < 4; mt++)
#pragma unroll
                    for (int nt = 0; nt < 4; nt++)
                        mma16816(acc[mt][nt], af[ah][mt],
                                 &bfr[bh][nt >> 1][(nt & 1) * 2]);
            }
        }
        __syncthreads();
    }

    // ---- epilogue ----
    const int tq = lane >> 2, tr = lane & 3;
#pragma unroll
    for (int nt = 0; nt < 4; nt++) {
        const int n = n0 + wn * 32 + nt * 8 + tr * 2;
        float b0 = 0.f, b1 = 0.f;
        if (HAS_BIAS) { b0 = bias[n]; b1 = bias[n + 1]; }
#pragma unroll
        for (int mt = 0; mt < 4; mt++) {
            const int m = m0 + wm * 64 + mt * 16 + tq;
            float2 o0, o1;
            o0.x = fmaf(alpha, acc[mt][nt][0], b0);
            o0.y = fmaf(alpha, acc[mt][nt][1], b1);
            o1.x = fmaf(alpha, acc[mt][nt][2], b0);
            o1.y = fmaf(alpha, acc[mt][nt][3], b1);
            *(float2*)(C + (long long)m * ldc + n)       = o0;
            *(float2*)(C + (long long)(m + 8) * ldc + n) = o1;
        }
    }
#undef LOAD_STAGE
}

// ---------------------------------------------------------------------------
// elementwise fp32 -> bf16 hi/lo split
// ---------------------------------------------------------------------------
__global__ __launch_bounds__(256)
void split_kernel(const float* __restrict__ in, bf16* __restrict__ oh,
                  bf16* __restrict__ ol)
{
    const size_t i = ((size_t)blockIdx.x * 256 + threadIdx.x) * 4;
    const float4 v = *(const float4*)(in + i);
    bf16 h0, h1, h2, h3, l0, l1, l2, l3;
    split1(v.x, h0, l0); split1(v.y, h1, l1);
    split1(v.z, h2, l2); split1(v.w, h3, l3);
    *(uint2*)(oh + i) = make_uint2(pack2(h0, h1), pack2(h2, h3));
    *(uint2*)(ol + i) = make_uint2(pack2(l0, l1), pack2(l2, l3));
}

// ---------------------------------------------------------------------------
// transpose + split:  in [R][C] (row stride ldin) -> oh/ol [C][R]
// ---------------------------------------------------------------------------
__global__ __launch_bounds__(256)
void transpose_split(const float* __restrict__ in, int ldin, long long sIn,
                     bf16* __restrict__ oh, bf16* __restrict__ ol,
                     int R, long long sOut)
{
    __shared__ float t[32][33];
    in += blockIdx.z * sIn;
    oh += blockIdx.z * sOut;
    ol += blockIdx.z * sOut;
    const int c0 = blockIdx.x * 32, r0 = blockIdx.y * 32;
    const int x = threadIdx.x, y = threadIdx.y;
#pragma unroll
    for (int j = 0; j < 32; j += 8)
        t[y + j][x] = in[(long long)(r0 + y + j) * ldin + c0 + x];
    __syncthreads();
#pragma unroll
    for (int j = 0; j < 32; j += 8) {
        const float v = t[x][y + j];
        bf16 h, l;
        split1(v, h, l);
        oh[(long long)(c0 + y + j) * R + r0 + x] = h;
        ol[(long long)(c0 + y + j) * R + r0 + x] = l;
    }
}

// ---------------------------------------------------------------------------
// row softmax over S (fp32) -> bf16 hi/lo outputs
// ---------------------------------------------------------------------------
__global__ __launch_bounds__(256)
void softmax_split_kernel(const float* __restrict__ S, bf16* __restrict__ Sh,
                          bf16* __restrict__ Sl)
{
    const size_t ro = (size_t)blockIdx.x * N_;
    const float* p = S + ro;
    const int tid = threadIdx.x;
    const int w = tid >> 5, l = tid & 31;

    float4 v[4];
#pragma unroll
    for (int i = 0; i < 4; i++)
        v[i] = *(const float4*)(p + (size_t)(tid + i * 256) * 4);

    float m = v[0].x;
#pragma unroll
    for (int i = 0; i < 4; i++) {
        m = fmaxf(m, v[i].x); m = fmaxf(m, v[i].y);
        m = fmaxf(m, v[i].z); m = fmaxf(m, v[i].w);
    }
#pragma unroll
    for (int o = 16; o > 0; o >>= 1)
        m = fmaxf(m, __shfl_xor_sync(0xffffffffu, m, o));

    __shared__ float red[8];
    if (l == 0) red[w] = m;
    __syncthreads();
    float bm = red[0];
#pragma unroll
    for (int i = 1; i < 8; i++) bm = fmaxf(bm, red[i]);
    __syncthreads();

    float s = 0.0f;
#pragma unroll
    for (int i = 0; i < 4; i++) {
        v[i].x = expf(v[i].x - bm); s += v[i].x;
        v[i].y = expf(v[i].y - bm); s += v[i].y;
        v[i].z = expf(v[i].z - bm); s += v[i].z;
        v[i].w = expf(v[i].w - bm); s += v[i].w;
    }
#pragma unroll
    for (int o = 16; o > 0; o >>= 1)
        s += __shfl_xor_sync(0xffffffffu, s, o);
    if (l == 0) red[w] = s;
    __syncthreads();
    float tot = red[0];
#pragma unroll
    for (int i = 1; i < 8; i++) tot += red[i];
    const float inv = 1.0f / tot;

#pragma unroll
    for (int i = 0; i < 4; i++) {
        const size_t o = ro + (size_t)(tid + i * 256) * 4;
        bf16 h0, h1, h2, h3, l0, l1, l2, l3;
        split1(v[i].x * inv, h0, l0);
        split1(v[i].y * inv, h1, l1);
        split1(v[i].z * inv, h2, l2);
        split1(v[i].w * inv, h3, l3);
        *(uint2*)(Sh + o) = make_uint2(pack2(h0, h1), pack2(h2, h3));
        *(uint2*)(Sl + o) = make_uint2(pack2(l0, l1), pack2(l2, l3));
    }
}

// ---------------------------------------------------------------------------
extern "C" void kernel_launch(void* const* d_in, const int* in_sizes, int n_in,
                              void* d_out, int out_size)
{
    const float* x     = (const float*)d_in[0];
    const float* w_qkv = (const float*)d_in[1];
    const float* b_qkv = (const float*)d_in[2];
    const float* w_out = (const float*)d_in[3];
    const float* b_out = (const float*)d_in[4];
    float* out = (float*)d_out;

    float *qkv, *S, *ctx;
    bf16 *xh, *xl, *qh, *ql, *sh, *sl, *vth, *vtl, *ch, *cl, *wqh, *wql, *woh, *wol;
    cudaGetSymbolAddress((void**)&qkv, g_qkv);
    cudaGetSymbolAddress((void**)&S,   g_s);
    cudaGetSymbolAddress((void**)&ctx, g_ctx);
    cudaGetSymbolAddress((void**)&xh,  g_xh);  cudaGetSymbolAddress((void**)&xl,  g_xl);
    cudaGetSymbolAddress((void**)&qh,  g_qh);  cudaGetSymbolAddress((void**)&ql,  g_ql);
    cudaGetSymbolAddress((void**)&sh,  g_sh);  cudaGetSymbolAddress((void**)&sl,  g_sl);
    cudaGetSymbolAddress((void**)&vth, g_vth); cudaGetSymbolAddress((void**)&vtl, g_vtl);
    cudaGetSymbolAddress((void**)&ch,  g_ch);  cudaGetSymbolAddress((void**)&cl,  g_cl);
    cudaGetSymbolAddress((void**)&wqh, g_wqh); cudaGetSymbolAddress((void**)&wql, g_wql);
    cudaGetSymbolAddress((void**)&woh, g_woh); cudaGetSymbolAddress((void**)&wol, g_wol);

    cudaFuncSetAttribute(mma_gemm<true>,
        cudaFuncAttributeMaxDynamicSharedMemorySize, SMEM_DYN);
    cudaFuncSetAttribute(mma_gemm<false>,
        cudaFuncAttributeMaxDynamicSharedMemorySize, SMEM_DYN);

    const dim3 blk(256);
    const dim3 tblk(32, 8);

    // operand prep
    split_kernel<<<(B_ * N_ * D_) / 1024, blk>>>(x, xh, xl);
    transpose_split<<<dim3(QKVC / 32, D_ / 32, 1), tblk>>>(
        w_qkv, QKVC, 0, wqh, wql, D_, 0);
    transpose_split<<<dim3(D_ / 32, D_ / 32, 1), tblk>>>(
        w_out, D_, 0, woh, wol, D_, 0);

    // 1) qkv = x @ w_qkv + b_qkv
    mma_gemm<true><<<dim3(QKVC / 128, (B_ * N_) / 128, 1), blk, SMEM_DYN>>>(
        xh, xl, wqh, wql, b_qkv, qkv, D_, D_, D_, QKVC, 0, 0, 0, 1.0f);

    split_kernel<<<(B_ * N_ * QKVC) / 1024, blk>>>(qkv, qh, ql);
    // V^T (per batch): qkv[b][n][2D..3D) -> [D][N]
    transpose_split<<<dim3(D_ / 32, N_ / 32, B_), tblk>>>(
        qkv + 2 * D_, QKVC, (long long)N_ * QKVC, vth, vtl, N_,
        (long long)D_ * N_);

    // 2) S = scale * Q @ K^T
    mma_gemm<false><<<dim3(N_ / 128, N_ / 128, B_), blk, SMEM_DYN>>>(
        qh, ql, qh + D_, ql + D_, nullptr, S, D_, QKVC, QKVC, N_,
        (long long)N_ * QKVC, (long long)N_ * QKVC, (long long)N_ * N_, SCALE_F);

    // 3) softmax + split
    softmax_split_kernel<<<B_ * N_, blk>>>(S, sh, sl);

    // 4) ctx = S @ V    (B operand = V^T rows, K-major)
    mma_gemm<false><<<dim3(D_ / 128, N_ / 128, B_), blk, SMEM_DYN>>>(
        sh, sl, vth, vtl, nullptr, ctx, N_, N_, N_, D_,
        (long long)N_ * N_, (long long)D_ * N_, (long long)N_ * D_, 1.0f);

    split_kernel<<<(B_ * N_ * D_) / 1024, blk>>>(ctx, ch, cl);

    // 5) out = ctx @ w_out + b_out
    mma_gemm<true><<<dim3(D_ / 128, (B_ * N_) / 128, 1), blk, SMEM_DYN>>>(
        ch, cl, woh, wol, b_out, out, D_, D_, D_, D_, 0, 0, 0, 1.0f);
}

// round 6
// speedup vs baseline: 2.7324x; 1.1671x over previous
#include <cuda_runtime.h>
#include <cuda_bf16.h>
#include <stdint.h>
#include <math.h>

// ---------------------------------------------------------------------------
// MySelfAttention_V2 (B=4, N=4096, D=768) — mma.sync bf16 hi/lo split (3-pass)
// GEMM: C = alpha * A*B^T (+bias), A,B as bf16 (hi,lo) pairs, fp32 accum:
//   A*B ≈ Ah*Bh + Ah*Bl + Al*Bh     (dropped term ~2^-18 rel)
// R6: 3-stage cp.async pipeline, XOR-swizzled smem (64B rows), one barrier
//     per K-chunk, hi/lo split fused into GEMM epilogues.
// ---------------------------------------------------------------------------

#define B_   4
#define N_   4096
#define D_   768
#define QKVC 2304
#define SCALE_F 0.03608439182435161f

typedef __nv_bfloat16 bf16;

// ---------------- scratch (static device globals: allocation-guard-safe) ----
__device__ float g_qkv [(size_t)B_ * N_ * QKVC];
__device__ float g_s   [(size_t)B_ * N_ * N_];
__device__ bf16  g_xh  [(size_t)B_ * N_ * D_],   g_xl  [(size_t)B_ * N_ * D_];
__device__ bf16  g_qh  [(size_t)B_ * N_ * QKVC], g_ql  [(size_t)B_ * N_ * QKVC];
__device__ bf16  g_sh  [(size_t)B_ * N_ * N_],   g_sl  [(size_t)B_ * N_ * N_];
__device__ bf16  g_vth [(size_t)B_ * D_ * N_],   g_vtl [(size_t)B_ * D_ * N_];
__device__ bf16  g_ch  [(size_t)B_ * N_ * D_],   g_cl  [(size_t)B_ * N_ * D_];
__device__ bf16  g_wqh [(size_t)QKVC * D_],      g_wql [(size_t)QKVC * D_];
__device__ bf16  g_woh [(size_t)D_ * D_],        g_wol [(size_t)D_ * D_];

// ---------------- PTX helpers ----------------------------------------------
static __device__ __forceinline__ uint32_t smem_u32(const void* p) {
    uint32_t a;
    asm("{ .reg .u64 t; cvta.to.shared.u64 t, %1; cvt.u32.u64 %0, t; }"
        : "=r"(a) : "l"(p));
    return a;
}
static __device__ __forceinline__ void cp_async16(uint32_t saddr, const void* g) {
    asm volatile("cp.async.cg.shared.global [%0], [%1], 16;"
                 :: "r"(saddr), "l"(g) : "memory");
}
static __device__ __forceinline__ void cp_commit() {
    asm volatile("cp.async.commit_group;" ::: "memory");
}
template <int N>
static __device__ __forceinline__ void cp_wait() {
    asm volatile("cp.async.wait_group %0;" :: "n"(N) : "memory");
}
static __device__ __forceinline__ void ldsm_x4(uint32_t* r, uint32_t addr) {
    asm volatile("ldmatrix.sync.aligned.m8n8.x4.shared.b16 {%0,%1,%2,%3}, [%4];"
                 : "=r"(r[0]), "=r"(r[1]), "=r"(r[2]), "=r"(r[3]) : "r"(addr));
}
static __device__ __forceinline__ void mma16816(float* c, const uint32_t* a,
                                                const uint32_t* b) {
    asm volatile(
        "mma.sync.aligned.m16n8k16.row.col.f32.bf16.bf16.f32 "
        "{%0,%1,%2,%3}, {%4,%5,%6,%7}, {%8,%9}, {%0,%1,%2,%3};"
        : "+f"(c[0]), "+f"(c[1]), "+f"(c[2]), "+f"(c[3])
        : "r"(a[0]), "r"(a[1]), "r"(a[2]), "r"(a[3]), "r"(b[0]), "r"(b[1]));
}
// hi/lo split of an fp32 into two bf16
static __device__ __forceinline__ void split1(float v, bf16& h, bf16& l) {
    h = __float2bfloat16_rn(v);
    l = __float2bfloat16_rn(v - __bfloat162float(h));
}
static __device__ __forceinline__ uint32_t pack2(bf16 a, bf16 b) {
    return (uint32_t)__bfloat16_as_ushort(a) |
           ((uint32_t)__bfloat16_as_ushort(b) << 16);
}

// XOR swizzle: logical (row, 16B-chunk) -> byte offset in 64B-row tile.
// Keeps 8-lane ldmatrix groups on 8 distinct 16B bank groups.
static __device__ __forceinline__ uint32_t swz(uint32_t row, uint32_t chunk) {
    return row * 64u + (((chunk ^ (row >> 1)) & 3u) << 4);
}

// ---------------------------------------------------------------------------
// GEMM: C[m,n] = alpha * sum_k A[m,k]*B[n,k]  (+bias[n])
// A,B bf16 hi/lo K-major. Tile 128x128, BK=32, 256 threads (2x4 warps),
// 3-stage cp.async pipeline, swizzled 64B smem rows.
// Optional fused outputs: fp32 C and/or bf16 hi/lo split (Oh/Ol).
// ---------------------------------------------------------------------------
#define TILE_B 8192                       // 128 rows * 64 B
#define STAGE_B (4 * TILE_B)              // Ah,Al,Bh,Bl
static const int SMEM_DYN = 3 * STAGE_B;  // 98304

template <bool HAS_BIAS, bool WRITE_F32, bool WRITE_SPLIT>
__global__ __launch_bounds__(256)
void mma_gemm(const bf16* __restrict__ Ah, const bf16* __restrict__ Al,
              const bf16* __restrict__ Bh, const bf16* __restrict__ Bl,
              const float* __restrict__ bias, float* __restrict__ C,
              bf16* __restrict__ Oh, bf16* __restrict__ Ol,
              int K, int lda, int ldb, int ldc,
              long long sA, long long sB, long long sC, float alpha)
{
    extern __shared__ char smem[];
    const uint32_t sb = smem_u32(smem);

    Ah += blockIdx.z * sA;  Al += blockIdx.z * sA;
    Bh += blockIdx.z * sB;  Bl += blockIdx.z * sB;
    const long long cz = blockIdx.z * sC;
    const int m0 = blockIdx.y * 128, n0 = blockIdx.x * 128;
    const int tid  = threadIdx.x;
    const int wid  = tid >> 5, lane = tid & 31;
    const int wm   = wid >> 2, wn = wid & 3;   // 2 x 4 warps

    // cp.async mapping: per matrix, 2x 16B per thread (rows r, r+64; chunk t&3)
    const int cr0 = tid >> 2, cc = tid & 3;
    const uint32_t so0 = swz((uint32_t)cr0, (uint32_t)cc);
    const uint32_t so1 = swz((uint32_t)(cr0 + 64), (uint32_t)cc);

#define LOAD_STAGE(st, k0)                                                      \
    do {                                                                        \
        const uint32_t s0 = sb + (uint32_t)(st) * STAGE_B;                      \
        const long long kof = (long long)(k0) + cc * 8;                         \
        cp_async16(s0 + 0*TILE_B + so0, Ah + (long long)(m0+cr0)    *lda + kof);\
        cp_async16(s0 + 0*TILE_B + so1, Ah + (long long)(m0+cr0+64) *lda + kof);\
        cp_async16(s0 + 1*TILE_B + so0, Al + (long long)(m0+cr0)    *lda + kof);\
        cp_async16(s0 + 1*TILE_B + so1, Al + (long long)(m0+cr0+64) *lda + kof);\
        cp_async16(s0 + 2*TILE_B + so0, Bh + (long long)(n0+cr0)    *ldb + kof);\
        cp_async16(s0 + 2*TILE_B + so1, Bh + (long long)(n0+cr0+64) *ldb + kof);\
        cp_async16(s0 + 3*TILE_B + so0, Bl + (long long)(n0+cr0)    *ldb + kof);\
        cp_async16(s0 + 3*TILE_B + so1, Bl + (long long)(n0+cr0+64) *ldb + kof);\
    } while (0)

    // ldmatrix lane-logical coordinates (same mapping as validated R5 kernel)
    const uint32_t a_row_l = (uint32_t)(lane & 15);
    const uint32_t a_chk_l = (uint32_t)(lane >> 4);
    const uint32_t b_row_l = (uint32_t)((lane & 7) + ((lane >> 4) << 3));
    const uint32_t b_chk_l = (uint32_t)((lane >> 3) & 1);

    float acc[4][4][4];
#pragma unroll
    for (int mt = 0; mt < 4; mt++)
#pragma unroll
        for (int nt = 0; nt < 4; nt++)
#pragma unroll
            for (int r = 0; r < 4; r++) acc[mt][nt][r] = 0.0f;

    const int nch = K / 32;
    LOAD_STAGE(0, 0);
    cp_commit();
    if (nch > 1) LOAD_STAGE(1, 32);
    cp_commit();

    int st = 0;                        // compute stage
    int ls = 2;                        // load stage
    for (int ch = 0; ch < nch; ch++) {
        cp_wait<1>();                  // stage `st` resident
        __syncthreads();               // all warps done with stage `ls` contents
        if (ch + 2 < nch) LOAD_STAGE(ls, (long long)(ch + 2) * 32);
        cp_commit();

        const uint32_t base = sb + (uint32_t)st * STAGE_B;
#pragma unroll
        for (int kk = 0; kk < 2; kk++) {
            uint32_t af[2][4][4];      // [hl][mt][reg]
            uint32_t bfr[2][2][4];     // [hl][pair][reg]
            const uint32_t a_chk = (uint32_t)(kk * 2) + a_chk_l;
            const uint32_t b_chk = (uint32_t)(kk * 2) + b_chk_l;
#pragma unroll
            for (int mt = 0; mt < 4; mt++) {
                const uint32_t ro = swz((uint32_t)(wm * 64 + mt * 16) + a_row_l, a_chk);
                ldsm_x4(af[0][mt], base + 0 * TILE_B + ro);
                ldsm_x4(af[1][mt], base + 1 * TILE_B + ro);
            }
#pragma unroll
            for (int p = 0; p < 2; p++) {
                const uint32_t ro = swz((uint32_t)(wn * 32 + p * 16) + b_row_l, b_chk);
                ldsm_x4(bfr[0][p], base + 2 * TILE_B + ro);
                ldsm_x4(bfr[1][p], base + 3 * TILE_B + ro);
            }
            // 3 passes: (Ah,Bh), (Ah,Bl), (Al,Bh)
#pragma unroll
            for (int ps = 0; ps < 3; ps++) {
                const int ah = (ps == 2), bh = (ps == 1);
#pragma unroll
                for (int mt = 0; mt < 4; mt++)
#pragma unroll
                    for (int nt = 0; nt < 4; nt++)
                        mma16816(acc[mt][nt], af[ah][mt],
                                 &bfr[bh][nt >> 1][(nt & 1) * 2]);
            }
        }
        st = (st == 2) ? 0 : st + 1;
        ls = (ls == 2) ? 0 : ls + 1;
    }

    // ---- epilogue ----
    const int tq = lane >> 2, tr = lane & 3;
#pragma unroll
    for (int nt = 0; nt < 4; nt++) {
        const int n = n0 + wn * 32 + nt * 8 + tr * 2;
        float b0 = 0.f, b1 = 0.f;
        if (HAS_BIAS) { b0 = bias[n]; b1 = bias[n + 1]; }
#pragma unroll
        for (int mt = 0; mt < 4; mt++) {
            const int m = m0 + wm * 64 + mt * 16 + tq;
            float2 o0, o1;
            o0.x = fmaf(alpha, acc[mt][nt][0], b0);
            o0.y = fmaf(alpha, acc[mt][nt][1], b1);
            o1.x = fmaf(alpha, acc[mt][nt][2], b0);
            o1.y = fmaf(alpha, acc[mt][nt][3], b1);
            const long long r0 = cz + (long long)m * ldc + n;
            const long long r1 = cz + (long long)(m + 8) * ldc + n;
            if (WRITE_F32) {
                *(float2*)(C + r0) = o0;
                *(float2*)(C + r1) = o1;
            }
            if (WRITE_SPLIT) {
                bf16 h0, l0, h1, l1;
                split1(o0.x, h0, l0); split1(o0.y, h1, l1);
                *(uint32_t*)(Oh + r0) = pack2(h0, h1);
                *(uint32_t*)(Ol + r0) = pack2(l0, l1);
                split1(o1.x, h0, l0); split1(o1.y, h1, l1);
                *(uint32_t*)(Oh + r1) = pack2(h0, h1);
                *(uint32_t*)(Ol + r1) = pack2(l0, l1);
            }
        }
    }
#undef LOAD_STAGE
}

// ---------------------------------------------------------------------------
// elementwise fp32 -> bf16 hi/lo split
// ---------------------------------------------------------------------------
__global__ __launch_bounds__(256)
void split_kernel(const float* __restrict__ in, bf16* __restrict__ oh,
                  bf16* __restrict__ ol)
{
    const size_t i = ((size_t)blockIdx.x * 256 + threadIdx.x) * 4;
    const float4 v = *(const float4*)(in + i);
    bf16 h0, h1, h2, h3, l0, l1, l2, l3;
    split1(v.x, h0, l0); split1(v.y, h1, l1);
    split1(v.z, h2, l2); split1(v.w, h3, l3);
    *(uint2*)(oh + i) = make_uint2(pack2(h0, h1), pack2(h2, h3));
    *(uint2*)(ol + i) = make_uint2(pack2(l0, l1), pack2(l2, l3));
}

// ---------------------------------------------------------------------------
// transpose + split:  in [R][C] (row stride ldin) -> oh/ol [C][R]
// ---------------------------------------------------------------------------
__global__ __launch_bounds__(256)
void transpose_split(const float* __restrict__ in, int ldin, long long sIn,
                     bf16* __restrict__ oh, bf16* __restrict__ ol,
                     int R, long long sOut)
{
    __shared__ float t[32][33];
    in += blockIdx.z * sIn;
    oh += blockIdx.z * sOut;
    ol += blockIdx.z * sOut;
    const int c0 = blockIdx.x * 32, r0 = blockIdx.y * 32;
    const int x = threadIdx.x, y = threadIdx.y;
#pragma unroll
    for (int j = 0; j < 32; j += 8)
        t[y + j][x] = in[(long long)(r0 + y + j) * ldin + c0 + x];
    __syncthreads();
#pragma unroll
    for (int j = 0; j < 32; j += 8) {
        const float v = t[x][y + j];
        bf16 h, l;
        split1(v, h, l);
        oh[(long long)(c0 + y + j) * R + r0 + x] = h;
        ol[(long long)(c0 + y + j) * R + r0 + x] = l;
    }
}

// ---------------------------------------------------------------------------
// row softmax over S (fp32) -> bf16 hi/lo outputs
// ---------------------------------------------------------------------------
__global__ __launch_bounds__(256)
void softmax_split_kernel(const float* __restrict__ S, bf16* __restrict__ Sh,
                          bf16* __restrict__ Sl)
{
    const size_t ro = (size_t)blockIdx.x * N_;
    const float* p = S + ro;
    const int tid = threadIdx.x;
    const int w = tid >> 5, l = tid & 31;

    float4 v[4];
#pragma unroll
    for (int i = 0; i < 4; i++)
        v[i] = *(const float4*)(p + (size_t)(tid + i * 256) * 4);

    float m = v[0].x;
#pragma unroll
    for (int i = 0; i < 4; i++) {
        m = fmaxf(m, v[i].x); m = fmaxf(m, v[i].y);
        m = fmaxf(m, v[i].z); m = fmaxf(m, v[i].w);
    }
#pragma unroll
    for (int o = 16; o > 0; o >>= 1)
        m = fmaxf(m, __shfl_xor_sync(0xffffffffu, m, o));

    __shared__ float red[8];
    if (l == 0) red[w] = m;
    __syncthreads();
    float bm = red[0];
#pragma unroll
    for (int i = 1; i < 8; i++) bm = fmaxf(bm, red[i]);
    __syncthreads();

    float s = 0.0f;
#pragma unroll
    for (int i = 0; i < 4; i++) {
        v[i].x = expf(v[i].x - bm); s += v[i].x;
        v[i].y = expf(v[i].y - bm); s += v[i].y;
        v[i].z = expf(v[i].z - bm); s += v[i].z;
        v[i].w = expf(v[i].w - bm); s += v[i].w;
    }
#pragma unroll
    for (int o = 16; o > 0; o >>= 1)
        s += __shfl_xor_sync(0xffffffffu, s, o);
    if (l == 0) red[w] = s;
    __syncthreads();
    float tot = red[0];
#pragma unroll
    for (int i = 1; i < 8; i++) tot += red[i];
    const float inv = 1.0f / tot;

#pragma unroll
    for (int i = 0; i < 4; i++) {
        const size_t o = ro + (size_t)(tid + i * 256) * 4;
        bf16 h0, h1, h2, h3, l0, l1, l2, l3;
        split1(v[i].x * inv, h0, l0);
        split1(v[i].y * inv, h1, l1);
        split1(v[i].z * inv, h2, l2);
        split1(v[i].w * inv, h3, l3);
        *(uint2*)(Sh + o) = make_uint2(pack2(h0, h1), pack2(h2, h3));
        *(uint2*)(Sl + o) = make_uint2(pack2(l0, l1), pack2(l2, l3));
    }
}

// ---------------------------------------------------------------------------
extern "C" void kernel_launch(void* const* d_in, const int* in_sizes, int n_in,
                              void* d_out, int out_size)
{
    const float* x     = (const float*)d_in[0];
    const float* w_qkv = (const float*)d_in[1];
    const float* b_qkv = (const float*)d_in[2];
    const float* w_out = (const float*)d_in[3];
    const float* b_out = (const float*)d_in[4];
    float* out = (float*)d_out;

    float *qkv, *S;
    bf16 *xh, *xl, *qh, *ql, *sh, *sl, *vth, *vtl, *ch, *cl, *wqh, *wql, *woh, *wol;
    cudaGetSymbolAddress((void**)&qkv, g_qkv);
    cudaGetSymbolAddress((void**)&S,   g_s);
    cudaGetSymbolAddress((void**)&xh,  g_xh);  cudaGetSymbolAddress((void**)&xl,  g_xl);
    cudaGetSymbolAddress((void**)&qh,  g_qh);  cudaGetSymbolAddress((void**)&ql,  g_ql);
    cudaGetSymbolAddress((void**)&sh,  g_sh);  cudaGetSymbolAddress((void**)&sl,  g_sl);
    cudaGetSymbolAddress((void**)&vth, g_vth); cudaGetSymbolAddress((void**)&vtl, g_vtl);
    cudaGetSymbolAddress((void**)&ch,  g_ch);  cudaGetSymbolAddress((void**)&cl,  g_cl);
    cudaGetSymbolAddress((void**)&wqh, g_wqh); cudaGetSymbolAddress((void**)&wql, g_wql);
    cudaGetSymbolAddress((void**)&woh, g_woh); cudaGetSymbolAddress((void**)&wol, g_wol);

    cudaFuncSetAttribute(mma_gemm<true, true, true>,
        cudaFuncAttributeMaxDynamicSharedMemorySize, SMEM_DYN);
    cudaFuncSetAttribute(mma_gemm<false, true, false>,
        cudaFuncAttributeMaxDynamicSharedMemorySize, SMEM_DYN);
    cudaFuncSetAttribute(mma_gemm<false, false, true>,
        cudaFuncAttributeMaxDynamicSharedMemorySize, SMEM_DYN);
    cudaFuncSetAttribute(mma_gemm<true, true, false>,
        cudaFuncAttributeMaxDynamicSharedMemorySize, SMEM_DYN);

    const dim3 blk(256);
    const dim3 tblk(32, 8);

    // operand prep
    split_kernel<<<(B_ * N_ * D_) / 1024, blk>>>(x, xh, xl);
    transpose_split<<<dim3(QKVC / 32, D_ / 32, 1), tblk>>>(
        w_qkv, QKVC, 0, wqh, wql, D_, 0);
    transpose_split<<<dim3(D_ / 32, D_ / 32, 1), tblk>>>(
        w_out, D_, 0, woh, wol, D_, 0);

    // 1) qkv = x @ w_qkv + b_qkv   (fp32 + fused hi/lo split)
    mma_gemm<true, true, true><<<dim3(QKVC / 128, (B_ * N_) / 128, 1), blk, SMEM_DYN>>>(
        xh, xl, wqh, wql, b_qkv, qkv, qh, ql, D_, D_, D_, QKVC, 0, 0, 0, 1.0f);

    // V^T (per batch): qkv[b][n][2D..3D) -> [D][N]
    transpose_split<<<dim3(D_ / 32, N_ / 32, B_), tblk>>>(
        qkv + 2 * D_, QKVC, (long long)N_ * QKVC, vth, vtl, N_,
        (long long)D_ * N_);

    // 2) S = scale * Q @ K^T
    mma_gemm<false, true, false><<<dim3(N_ / 128, N_ / 128, B_), blk, SMEM_DYN>>>(
        qh, ql, qh + D_, ql + D_, nullptr, S, nullptr, nullptr, D_, QKVC, QKVC, N_,
        (long long)N_ * QKVC, (long long)N_ * QKVC, (long long)N_ * N_, SCALE_F);

    // 3) softmax + split
    softmax_split_kernel<<<B_ * N_, blk>>>(S, sh, sl);

    // 4) ctx = S @ V   (hi/lo split only, no fp32 intermediate)
    mma_gemm<false, false, true><<<dim3(D_ / 128, N_ / 128, B_), blk, SMEM_DYN>>>(
        sh, sl, vth, vtl, nullptr, nullptr, ch, cl, N_, N_, N_, D_,
        (long long)N_ * N_, (long long)D_ * N_, (long long)N_ * D_, 1.0f);

    // 5) out = ctx @ w_out + b_out
    mma_gemm<true, true, false><<<dim3(D_ / 128, (B_ * N_) / 128, 1), blk, SMEM_DYN>>>(
        ch, cl, woh, wol, b_out, out, nullptr, nullptr, D_, D_, D_, D_, 0, 0, 0, 1.0f);
}